// round 2
// baseline (speedup 1.0000x reference)
#include <cuda_runtime.h>

#define N_NODES 100000
#define IN_DIM  128
#define OUT_DIM 32
#define HEADS   8
#define HF      256   // HEADS*OUT_DIM
#define NEG_SLOPE 0.2f

// ---------------- scratch (static device globals; no allocation) ----------------
__device__ float g_h[N_NODES * HF];          // projected features, [N, H, F] row-major
__device__ float g_asrc[N_NODES * HEADS];    // per-node src logits
__device__ float g_adst[N_NODES * HEADS];    // per-node dst logits
__device__ float g_denom[N_NODES * HEADS];   // softmax denominators
__device__ int   g_is64;                     // 1 if edge_index is int64, 0 if int32

// ---------------- K0: probe edge_index dtype ----------------
// If the buffer is int32, reading it as int64 fuses index pairs into values
// >= 2^32 (unless the high word is 0, p=1e-5 per word). 64 words -> certainty.
__global__ void detect_kernel(const void* EI) {
    const long long* p = (const long long*)EI;
    int is64 = 1;
    #pragma unroll
    for (int i = 0; i < 64; i++) {
        long long v = p[i];
        if (v < 0 || v >= N_NODES) is64 = 0;
    }
    g_is64 = is64;
}

__device__ __forceinline__ void load_edge(const void* EI, long long e, int E,
                                          int is64, int& s, int& d) {
    if (is64) {
        const long long* p = (const long long*)EI;
        s = (int)p[e]; d = (int)p[e + E];
    } else {
        const int* p = (const int*)EI;
        s = p[e]; d = p[e + E];
    }
}

// ---------------- K1: h = X @ W  (100000x128 @ 128x256) ----------------
#define BM 64
#define BN 64
#define BK 64

__global__ void gemm_kernel(const float* __restrict__ X, const float* __restrict__ W) {
    __shared__ float As[BM][BK + 4];
    __shared__ float Bs[BK][BN];

    const int tid = threadIdx.x;          // 0..255
    const int tx = tid & 15;
    const int ty = tid >> 4;
    const int row0 = blockIdx.x * BM;
    const int col0 = blockIdx.y * BN;

    float acc[4][4] = {};

    for (int kk = 0; kk < IN_DIM; kk += BK) {
        #pragma unroll
        for (int i = 0; i < 4; i++) {
            int idx = tid + i * 256;
            int r  = idx >> 4;
            int c4 = idx & 15;
            float4 v = make_float4(0.f, 0.f, 0.f, 0.f);
            int gr = row0 + r;
            if (gr < N_NODES)
                v = *(const float4*)&X[(long long)gr * IN_DIM + kk + c4 * 4];
            *(float4*)&As[r][c4 * 4] = v;
        }
        #pragma unroll
        for (int i = 0; i < 4; i++) {
            int idx = tid + i * 256;
            int r  = idx >> 4;
            int c4 = idx & 15;
            float4 v = *(const float4*)&W[(long long)(kk + r) * HF + col0 + c4 * 4];
            *(float4*)&Bs[r][c4 * 4] = v;
        }
        __syncthreads();

        #pragma unroll
        for (int k = 0; k < BK; k++) {
            float a[4];
            #pragma unroll
            for (int i = 0; i < 4; i++) a[i] = As[ty * 4 + i][k];
            float4 bv = *(float4*)&Bs[k][tx * 4];
            float b[4] = {bv.x, bv.y, bv.z, bv.w};
            #pragma unroll
            for (int i = 0; i < 4; i++)
                #pragma unroll
                for (int j = 0; j < 4; j++)
                    acc[i][j] += a[i] * b[j];
        }
        __syncthreads();
    }

    #pragma unroll
    for (int i = 0; i < 4; i++) {
        int gr = row0 + ty * 4 + i;
        if (gr < N_NODES) {
            float4 v = make_float4(acc[i][0], acc[i][1], acc[i][2], acc[i][3]);
            *(float4*)&g_h[(long long)gr * HF + col0 + tx * 4] = v;
        }
    }
}

// ---------------- K2: per-node attention logits (warp per node) ----------------
__global__ void att_kernel(const float* __restrict__ att_src,
                           const float* __restrict__ att_dst) {
    int warp = (blockIdx.x * blockDim.x + threadIdx.x) >> 5;
    int lane = threadIdx.x & 31;
    if (warp >= N_NODES) return;
    const float* hrow = &g_h[(long long)warp * HF];
    #pragma unroll
    for (int c = 0; c < HEADS; c++) {
        float v = hrow[c * 32 + lane];
        float s = v * att_src[c * 32 + lane];
        float d = v * att_dst[c * 32 + lane];
        #pragma unroll
        for (int o = 16; o > 0; o >>= 1) {
            s += __shfl_down_sync(0xffffffffu, s, o);
            d += __shfl_down_sync(0xffffffffu, d, o);
        }
        if (lane == 0) {
            g_asrc[warp * HEADS + c] = s;
            g_adst[warp * HEADS + c] = d;
        }
    }
}

// ---------------- K3: zero denom, init out with bias ----------------
__global__ void init_kernel(float* __restrict__ out, const float* __restrict__ bias) {
    int i = blockIdx.x * blockDim.x + threadIdx.x;
    if (i < N_NODES * HEADS) g_denom[i] = 0.f;
    if (i < N_NODES * OUT_DIM) out[i] = bias[i & (OUT_DIM - 1)];
}

// ---------------- K4: softmax denominators (thread per edge, incl. self loops) ----
// Max-shift is skipped: logits are O(10), exp cannot overflow; the ratio is
// identical to the max-shifted form to ~1e-7.
__global__ void denom_kernel(const void* __restrict__ EI, int E) {
    int e = blockIdx.x * blockDim.x + threadIdx.x;
    int total = E + N_NODES;
    if (e >= total) return;
    int s, d;
    if (e < E) load_edge(EI, e, E, g_is64, s, d);
    else       s = d = e - E;

    const float4* as = (const float4*)&g_asrc[s * HEADS];
    const float4* ad = (const float4*)&g_adst[d * HEADS];
    float4 as0 = as[0], as1 = as[1];
    float4 ad0 = ad[0], ad1 = ad[1];
    float ev[8] = {as0.x + ad0.x, as0.y + ad0.y, as0.z + ad0.z, as0.w + ad0.w,
                   as1.x + ad1.x, as1.y + ad1.y, as1.z + ad1.z, as1.w + ad1.w};
    #pragma unroll
    for (int h = 0; h < HEADS; h++) {
        float x = ev[h];
        x = (x > 0.f) ? x : NEG_SLOPE * x;
        atomicAdd(&g_denom[d * HEADS + h], __expf(x));
    }
}

// ---------------- K5: weighted aggregation (warp per edge, lane = feature) ------
__global__ void agg_kernel(const void* __restrict__ EI,
                           float* __restrict__ out, int E) {
    long long gtid = (long long)blockIdx.x * blockDim.x + threadIdx.x;
    long long wid = gtid >> 5;
    int lane = threadIdx.x & 31;
    long long total = (long long)E + N_NODES;
    if (wid >= total) return;
    int s, d;
    if (wid < E) load_edge(EI, wid, E, g_is64, s, d);
    else         s = d = (int)(wid - E);

    float alpha = 0.f;
    if (lane < HEADS) {
        float x = g_asrc[s * HEADS + lane] + g_adst[d * HEADS + lane];
        x = (x > 0.f) ? x : NEG_SLOPE * x;
        alpha = __expf(x) / (g_denom[d * HEADS + lane] + 1e-16f) * (1.0f / HEADS);
    }

    const float* hrow = &g_h[(long long)s * HF];
    float acc = 0.f;
    #pragma unroll
    for (int h = 0; h < HEADS; h++) {
        float a = __shfl_sync(0xffffffffu, alpha, h);
        acc += a * __ldg(&hrow[h * 32 + lane]);
    }
    atomicAdd(&out[d * OUT_DIM + lane], acc);
}

// ---------------- launch ----------------
extern "C" void kernel_launch(void* const* d_in, const int* in_sizes, int n_in,
                              void* d_out, int out_size) {
    const float* X       = (const float*)d_in[0];
    const void*  EI      = d_in[1];
    const float* W       = (const float*)d_in[2];
    const float* att_src = (const float*)d_in[3];
    const float* att_dst = (const float*)d_in[4];
    const float* bias    = (const float*)d_in[5];
    float* out = (float*)d_out;

    int E = in_sizes[1] / 2;

    detect_kernel<<<1, 1>>>(EI);

    dim3 ggrid((N_NODES + BM - 1) / BM, HF / BN);
    gemm_kernel<<<ggrid, 256>>>(X, W);

    att_kernel<<<(N_NODES * 32 + 255) / 256, 256>>>(att_src, att_dst);

    init_kernel<<<(N_NODES * OUT_DIM + 255) / 256, 256>>>(out, bias);

    int total = E + N_NODES;
    denom_kernel<<<(total + 255) / 256, 256>>>(EI, E);

    long long agg_threads = (long long)total * 32;
    agg_kernel<<<(unsigned)((agg_threads + 255) / 256), 256>>>(EI, out, E);
}

// round 3
// speedup vs baseline: 1.2085x; 1.2085x over previous
#include <cuda_runtime.h>
#include <cuda_bf16.h>
#include <cstdint>

#define N_NODES 100000
#define IN_DIM  128
#define OUT_DIM 32
#define HEADS   8
#define HF      256   // HEADS*OUT_DIM
#define NEG_SLOPE 0.2f

// ---------------- scratch (static device globals; no allocation) ----------------
__device__ float g_h[(size_t)N_NODES * HF];      // projected features [N, H*F]
__device__ float g_asrc[N_NODES * HEADS];
__device__ float g_adst[N_NODES * HEADS];
__device__ float g_denom[N_NODES * HEADS];
__device__ int   g_is64;
__device__ __nv_bfloat16 g_Ah[(size_t)N_NODES * IN_DIM];  // hi split of X
__device__ __nv_bfloat16 g_Al[(size_t)N_NODES * IN_DIM];  // lo split of X
__device__ __nv_bfloat16 g_Bth[HF * IN_DIM];              // W^T hi: [n][k]
__device__ __nv_bfloat16 g_Btl[HF * IN_DIM];              // W^T lo: [n][k]

// ---------------- K0: probe edge_index dtype ----------------
__global__ void detect_kernel(const void* EI) {
    const long long* p = (const long long*)EI;
    int is64 = 1;
    #pragma unroll
    for (int i = 0; i < 64; i++) {
        long long v = p[i];
        if (v < 0 || v >= N_NODES) is64 = 0;
    }
    g_is64 = is64;
}

__device__ __forceinline__ void load_edge(const void* EI, long long e, int E,
                                          int is64, int& s, int& d) {
    if (is64) {
        const long long* p = (const long long*)EI;
        s = (int)p[e]; d = (int)p[e + E];
    } else {
        const int* p = (const int*)EI;
        s = p[e]; d = p[e + E];
    }
}

// ---------------- K1a: split X into bf16 hi/lo + init out/denom ----------------
__global__ void prep_kernel(const float* __restrict__ X,
                            const float* __restrict__ bias,
                            float* __restrict__ out) {
    int i = blockIdx.x * blockDim.x + threadIdx.x;   // 0 .. 3,199,999
    if (i < N_NODES * IN_DIM / 4) {
        float4 v = ((const float4*)X)[i];
        __nv_bfloat16 h0 = __float2bfloat16(v.x);
        __nv_bfloat16 h1 = __float2bfloat16(v.y);
        __nv_bfloat16 h2 = __float2bfloat16(v.z);
        __nv_bfloat16 h3 = __float2bfloat16(v.w);
        __nv_bfloat16 l0 = __float2bfloat16(v.x - __bfloat162float(h0));
        __nv_bfloat16 l1 = __float2bfloat16(v.y - __bfloat162float(h1));
        __nv_bfloat16 l2 = __float2bfloat16(v.z - __bfloat162float(h2));
        __nv_bfloat16 l3 = __float2bfloat16(v.w - __bfloat162float(h3));
        ((__nv_bfloat162*)g_Ah)[2 * i]     = __nv_bfloat162(h0, h1);
        ((__nv_bfloat162*)g_Ah)[2 * i + 1] = __nv_bfloat162(h2, h3);
        ((__nv_bfloat162*)g_Al)[2 * i]     = __nv_bfloat162(l0, l1);
        ((__nv_bfloat162*)g_Al)[2 * i + 1] = __nv_bfloat162(l2, l3);
    }
    if (i < N_NODES * OUT_DIM) out[i] = bias[i & (OUT_DIM - 1)];
    if (i < N_NODES * HEADS)   g_denom[i] = 0.f;
}

// ---------------- K1b: split + transpose W: [k][n] -> Wt[n][k] hi/lo ----------
__global__ void prepW_kernel(const float* __restrict__ W) {
    int i = blockIdx.x * blockDim.x + threadIdx.x;   // k*256 + n
    if (i >= IN_DIM * HF) return;
    int k = i >> 8;
    int n = i & 255;
    float x = W[i];
    __nv_bfloat16 hi = __float2bfloat16(x);
    __nv_bfloat16 lo = __float2bfloat16(x - __bfloat162float(hi));
    g_Bth[n * IN_DIM + k] = hi;
    g_Btl[n * IN_DIM + k] = lo;
}

// ---------------- K2: split-bf16 tensor-core GEMM + fused attention logits ----
// C(128x64 per block) = Xh*Wh + Xl*Wh + Xh*Wl, fp32 accum, via mma.m16n8k16.
#define GBM 128
#define GBN 64
#define GBK 64
#define SKP 72   // padded k-stride in bf16 (144B: 4r mod 32 bank rotation)

__device__ __forceinline__ void ldsm_x4(uint32_t& r0, uint32_t& r1,
                                        uint32_t& r2, uint32_t& r3, uint32_t addr) {
    asm volatile("ldmatrix.sync.aligned.m8n8.x4.shared.b16 {%0,%1,%2,%3}, [%4];\n"
                 : "=r"(r0), "=r"(r1), "=r"(r2), "=r"(r3) : "r"(addr));
}

__device__ __forceinline__ void mma_bf16(float c[4], const uint32_t a[4],
                                         const uint32_t b[2]) {
    asm volatile(
        "mma.sync.aligned.m16n8k16.row.col.f32.bf16.bf16.f32 "
        "{%0,%1,%2,%3},{%4,%5,%6,%7},{%8,%9},{%0,%1,%2,%3};\n"
        : "+f"(c[0]), "+f"(c[1]), "+f"(c[2]), "+f"(c[3])
        : "r"(a[0]), "r"(a[1]), "r"(a[2]), "r"(a[3]), "r"(b[0]), "r"(b[1]));
}

__global__ __launch_bounds__(256, 2)
void gemm_bf16_kernel(const float* __restrict__ att_src,
                      const float* __restrict__ att_dst) {
    __shared__ __align__(16) __nv_bfloat16 sA[GBM][SKP];
    __shared__ __align__(16) __nv_bfloat16 sB[GBN][SKP];

    const int tid  = threadIdx.x;
    const int lane = tid & 31;
    const int warp = tid >> 5;
    const int wm = (warp & 3) * 32;   // warp m-offset in block
    const int wn = (warp >> 2) * 32;  // warp n-offset in block (= one head)
    const int row0 = blockIdx.x * GBM;
    const int n0   = blockIdx.y * GBN;

    const uint32_t baseA = (uint32_t)__cvta_generic_to_shared(&sA[0][0]);
    const uint32_t baseB = (uint32_t)__cvta_generic_to_shared(&sB[0][0]);

    float acc[2][4][4];
    #pragma unroll
    for (int i = 0; i < 2; i++)
        #pragma unroll
        for (int j = 0; j < 4; j++)
            #pragma unroll
            for (int e = 0; e < 4; e++) acc[i][j][e] = 0.f;

    #pragma unroll 1
    for (int seg = 0; seg < 3; seg++) {
        const __nv_bfloat16* Aseg = (seg == 1) ? g_Al : g_Ah;
        const __nv_bfloat16* Bseg = (seg == 2) ? g_Btl : g_Bth;
        #pragma unroll 1
        for (int chunk = 0; chunk < 2; chunk++) {
            const int kk = chunk * GBK;
            __syncthreads();
            // load A tile: 128 rows x 64 k (8 x uint4 per row)
            #pragma unroll
            for (int it = 0; it < 4; it++) {
                int slot = tid + it * 256;
                int r  = slot >> 3;
                int c8 = (slot & 7) * 8;
                uint4 v = make_uint4(0u, 0u, 0u, 0u);
                int gr = row0 + r;
                if (gr < N_NODES)
                    v = *(const uint4*)&Aseg[(size_t)gr * IN_DIM + kk + c8];
                *(uint4*)&sA[r][c8] = v;
            }
            // load B tile: 64 n-rows x 64 k
            #pragma unroll
            for (int it = 0; it < 2; it++) {
                int slot = tid + it * 256;
                int r  = slot >> 3;
                int c8 = (slot & 7) * 8;
                uint4 v = *(const uint4*)&Bseg[(size_t)(n0 + r) * IN_DIM + kk + c8];
                *(uint4*)&sB[r][c8] = v;
            }
            __syncthreads();

            #pragma unroll
            for (int k0 = 0; k0 < GBK; k0 += 16) {
                uint32_t a[2][4];
                #pragma unroll
                for (int i = 0; i < 2; i++) {
                    int r = wm + 16 * i + (lane & 15);
                    int c = k0 + ((lane & 16) ? 8 : 0);
                    ldsm_x4(a[i][0], a[i][1], a[i][2], a[i][3],
                            baseA + (uint32_t)(r * SKP + c) * 2u);
                }
                uint32_t b[4][2];
                #pragma unroll
                for (int jj = 0; jj < 2; jj++) {
                    int r = wn + jj * 16 + (lane & 7) + ((lane & 16) ? 8 : 0);
                    int c = k0 + ((lane & 8) ? 8 : 0);
                    uint32_t r0, r1, r2, r3;
                    ldsm_x4(r0, r1, r2, r3, baseB + (uint32_t)(r * SKP + c) * 2u);
                    b[2 * jj][0] = r0; b[2 * jj][1] = r1;
                    b[2 * jj + 1][0] = r2; b[2 * jj + 1][1] = r3;
                }
                #pragma unroll
                for (int i = 0; i < 2; i++)
                    #pragma unroll
                    for (int j = 0; j < 4; j++)
                        mma_bf16(acc[i][j], a[i], b[j]);
            }
        }
    }

    // ---- epilogue: store h + fused per-head attention logits ----
    const int g   = lane >> 2;
    const int tig = lane & 3;
    const int head = blockIdx.y * 2 + (wn >> 5);

    float as_v[4][2], ad_v[4][2];
    #pragma unroll
    for (int j = 0; j < 4; j++) {
        int col = j * 8 + 2 * tig;   // col within head (0..31)
        as_v[j][0] = att_src[head * 32 + col];
        as_v[j][1] = att_src[head * 32 + col + 1];
        ad_v[j][0] = att_dst[head * 32 + col];
        ad_v[j][1] = att_dst[head * 32 + col + 1];
    }

    float ps[4] = {0.f, 0.f, 0.f, 0.f}, pd[4] = {0.f, 0.f, 0.f, 0.f};
    #pragma unroll
    for (int i = 0; i < 2; i++) {
        int row1 = row0 + wm + 16 * i + g;
        int row2 = row1 + 8;
        #pragma unroll
        for (int j = 0; j < 4; j++) {
            int colg = n0 + wn + j * 8 + 2 * tig;
            if (row1 < N_NODES)
                *(float2*)&g_h[(size_t)row1 * HF + colg] =
                    make_float2(acc[i][j][0], acc[i][j][1]);
            if (row2 < N_NODES)
                *(float2*)&g_h[(size_t)row2 * HF + colg] =
                    make_float2(acc[i][j][2], acc[i][j][3]);
            ps[2 * i]     += acc[i][j][0] * as_v[j][0] + acc[i][j][1] * as_v[j][1];
            ps[2 * i + 1] += acc[i][j][2] * as_v[j][0] + acc[i][j][3] * as_v[j][1];
            pd[2 * i]     += acc[i][j][0] * ad_v[j][0] + acc[i][j][1] * ad_v[j][1];
            pd[2 * i + 1] += acc[i][j][2] * ad_v[j][0] + acc[i][j][3] * ad_v[j][1];
        }
    }
    // reduce over the 4 threads (tig) sharing each row
    #pragma unroll
    for (int s = 0; s < 4; s++) {
        ps[s] += __shfl_xor_sync(0xffffffffu, ps[s], 1);
        ps[s] += __shfl_xor_sync(0xffffffffu, ps[s], 2);
        pd[s] += __shfl_xor_sync(0xffffffffu, pd[s], 1);
        pd[s] += __shfl_xor_sync(0xffffffffu, pd[s], 2);
    }
    if (tig == 0) {
        #pragma unroll
        for (int s = 0; s < 4; s++) {
            int row = row0 + wm + 16 * (s >> 1) + 8 * (s & 1) + g;
            if (row < N_NODES) {
                g_asrc[row * HEADS + head] = ps[s];
                g_adst[row * HEADS + head] = pd[s];
            }
        }
    }
}

// ---------------- K3: softmax denominators (thread per edge + self loops) -----
// Max-shift skipped: logits are O(10); exp cannot overflow; ratio identical.
__global__ void denom_kernel(const void* __restrict__ EI, int E) {
    int e = blockIdx.x * blockDim.x + threadIdx.x;
    int total = E + N_NODES;
    if (e >= total) return;
    int s, d;
    if (e < E) load_edge(EI, e, E, g_is64, s, d);
    else       s = d = e - E;

    const float4* as = (const float4*)&g_asrc[s * HEADS];
    const float4* ad = (const float4*)&g_adst[d * HEADS];
    float4 as0 = as[0], as1 = as[1];
    float4 ad0 = ad[0], ad1 = ad[1];
    float ev[8] = {as0.x + ad0.x, as0.y + ad0.y, as0.z + ad0.z, as0.w + ad0.w,
                   as1.x + ad1.x, as1.y + ad1.y, as1.z + ad1.z, as1.w + ad1.w};
    #pragma unroll
    for (int h = 0; h < HEADS; h++) {
        float x = ev[h];
        x = (x > 0.f) ? x : NEG_SLOPE * x;
        atomicAdd(&g_denom[d * HEADS + h], __expf(x));
    }
}

// ---------------- K4: weighted aggregation (warp per edge, lane = feature) ----
__global__ void agg_kernel(const void* __restrict__ EI,
                           float* __restrict__ out, int E) {
    long long gtid = (long long)blockIdx.x * blockDim.x + threadIdx.x;
    long long wid = gtid >> 5;
    int lane = threadIdx.x & 31;
    long long total = (long long)E + N_NODES;
    if (wid >= total) return;
    int s, d;
    if (wid < E) load_edge(EI, wid, E, g_is64, s, d);
    else         s = d = (int)(wid - E);

    float alpha = 0.f;
    if (lane < HEADS) {
        float x = g_asrc[s * HEADS + lane] + g_adst[d * HEADS + lane];
        x = (x > 0.f) ? x : NEG_SLOPE * x;
        alpha = __expf(x) / (g_denom[d * HEADS + lane] + 1e-16f) * (1.0f / HEADS);
    }

    const float* hrow = &g_h[(size_t)s * HF];
    float acc = 0.f;
    #pragma unroll
    for (int h = 0; h < HEADS; h++) {
        float a = __shfl_sync(0xffffffffu, alpha, h);
        acc += a * __ldg(&hrow[h * 32 + lane]);
    }
    atomicAdd(&out[d * OUT_DIM + lane], acc);
}

// ---------------- launch ----------------
extern "C" void kernel_launch(void* const* d_in, const int* in_sizes, int n_in,
                              void* d_out, int out_size) {
    const float* X       = (const float*)d_in[0];
    const void*  EI      = d_in[1];
    const float* W       = (const float*)d_in[2];
    const float* att_src = (const float*)d_in[3];
    const float* att_dst = (const float*)d_in[4];
    const float* bias    = (const float*)d_in[5];
    float* out = (float*)d_out;

    int E = in_sizes[1] / 2;

    detect_kernel<<<1, 1>>>(EI);

    prep_kernel<<<(N_NODES * IN_DIM / 4 + 255) / 256, 256>>>(X, bias, out);
    prepW_kernel<<<(IN_DIM * HF + 255) / 256, 256>>>(W);

    dim3 ggrid((N_NODES + GBM - 1) / GBM, HF / GBN);
    gemm_bf16_kernel<<<ggrid, 256>>>(att_src, att_dst);

    int total = E + N_NODES;
    denom_kernel<<<(total + 255) / 256, 256>>>(EI, E);

    long long agg_threads = (long long)total * 32;
    agg_kernel<<<(unsigned)((agg_threads + 255) / 256), 256>>>(EI, out, E);
}

// round 4
// speedup vs baseline: 1.5837x; 1.3105x over previous
#include <cuda_runtime.h>
#include <cuda_bf16.h>
#include <cstdint>

#define N_NODES 100000
#define IN_DIM  128
#define OUT_DIM 32
#define HEADS   8
#define HF      256   // HEADS*OUT_DIM
#define NEG_SLOPE 0.2f
#define MAX_SLOTS 1800000   // >= E + N_NODES

// ---------------- scratch (static device globals; no allocation) ----------------
__device__ float g_h[(size_t)N_NODES * HF];      // projected features [N, H*F]
__device__ float g_asrc[N_NODES * HEADS];
__device__ float g_adst[N_NODES * HEADS];
__device__ int   g_is64;
__device__ __nv_bfloat16 g_Ah[(size_t)N_NODES * IN_DIM];
__device__ __nv_bfloat16 g_Al[(size_t)N_NODES * IN_DIM];
__device__ __nv_bfloat16 g_Bth[HF * IN_DIM];
__device__ __nv_bfloat16 g_Btl[HF * IN_DIM];
// counting sort by destination
__device__ int g_cnt[N_NODES];
__device__ int g_off[N_NODES + 1];
__device__ int g_cur[N_NODES];
__device__ int g_bsum[128];
__device__ int g_boff[128];
__device__ int g_ssrc[MAX_SLOTS];

// ---------------- K0: probe edge_index dtype ----------------
__global__ void detect_kernel(const void* EI) {
    const long long* p = (const long long*)EI;
    int is64 = 1;
    #pragma unroll
    for (int i = 0; i < 64; i++) {
        long long v = p[i];
        if (v < 0 || v >= N_NODES) is64 = 0;
    }
    g_is64 = is64;
}

__device__ __forceinline__ void load_edge(const void* EI, long long e, int E,
                                          int is64, int& s, int& d) {
    if (is64) {
        const long long* p = (const long long*)EI;
        s = (int)p[e]; d = (int)p[e + E];
    } else {
        const int* p = (const int*)EI;
        s = p[e]; d = p[e + E];
    }
}

// ---------------- K1a: split X into bf16 hi/lo + init degree counts ----------
__global__ void prep_kernel(const float* __restrict__ X) {
    int i = blockIdx.x * blockDim.x + threadIdx.x;
    if (i < N_NODES * IN_DIM / 4) {
        float4 v = ((const float4*)X)[i];
        __nv_bfloat16 h0 = __float2bfloat16(v.x);
        __nv_bfloat16 h1 = __float2bfloat16(v.y);
        __nv_bfloat16 h2 = __float2bfloat16(v.z);
        __nv_bfloat16 h3 = __float2bfloat16(v.w);
        __nv_bfloat16 l0 = __float2bfloat16(v.x - __bfloat162float(h0));
        __nv_bfloat16 l1 = __float2bfloat16(v.y - __bfloat162float(h1));
        __nv_bfloat16 l2 = __float2bfloat16(v.z - __bfloat162float(h2));
        __nv_bfloat16 l3 = __float2bfloat16(v.w - __bfloat162float(h3));
        ((__nv_bfloat162*)g_Ah)[2 * i]     = __nv_bfloat162(h0, h1);
        ((__nv_bfloat162*)g_Ah)[2 * i + 1] = __nv_bfloat162(h2, h3);
        ((__nv_bfloat162*)g_Al)[2 * i]     = __nv_bfloat162(l0, l1);
        ((__nv_bfloat162*)g_Al)[2 * i + 1] = __nv_bfloat162(l2, l3);
    }
    if (i < N_NODES) g_cnt[i] = 1;   // self loop
}

// ---------------- K1b: split + transpose W ----------------
__global__ void prepW_kernel(const float* __restrict__ W) {
    int i = blockIdx.x * blockDim.x + threadIdx.x;
    if (i >= IN_DIM * HF) return;
    int k = i >> 8;
    int n = i & 255;
    float x = W[i];
    __nv_bfloat16 hi = __float2bfloat16(x);
    __nv_bfloat16 lo = __float2bfloat16(x - __bfloat162float(hi));
    g_Bth[n * IN_DIM + k] = hi;
    g_Btl[n * IN_DIM + k] = lo;
}

// ---------------- sort: histogram ----------------
__global__ void hist_kernel(const void* __restrict__ EI, int E) {
    int e = blockIdx.x * blockDim.x + threadIdx.x;
    if (e >= E) return;
    int s, d;
    load_edge(EI, e, E, g_is64, s, d);
    atomicAdd(&g_cnt[d], 1);
}

// ---------------- sort: hierarchical exclusive scan ----------------
__device__ __forceinline__ int block_scan_excl(int x, int* total) {
    // 1024-thread block inclusive scan; returns exclusive value, sets *total.
    int lane = threadIdx.x & 31, w = threadIdx.x >> 5;
    int v = x;
    #pragma unroll
    for (int o = 1; o < 32; o <<= 1) {
        int t = __shfl_up_sync(0xffffffffu, v, o);
        if (lane >= o) v += t;
    }
    __shared__ int ws[32];
    if (lane == 31) ws[w] = v;
    __syncthreads();
    if (w == 0) {
        int u = ws[lane];
        #pragma unroll
        for (int o = 1; o < 32; o <<= 1) {
            int t = __shfl_up_sync(0xffffffffu, u, o);
            if (lane >= o) u += t;
        }
        ws[lane] = u;
    }
    __syncthreads();
    int incl = v + (w > 0 ? ws[w - 1] : 0);
    *total = ws[31];
    return incl - x;
}

__global__ void scan1_kernel() {
    int i = blockIdx.x * 1024 + threadIdx.x;
    int x = (i < N_NODES) ? g_cnt[i] : 0;
    int total;
    int ex = block_scan_excl(x, &total);
    if (i < N_NODES) g_off[i] = ex;
    if (threadIdx.x == 0) g_bsum[blockIdx.x] = total;
}

__global__ void scan2_kernel(int nb, int E) {
    int b = threadIdx.x;
    int x = (b < nb) ? g_bsum[b] : 0;
    int total;
    int ex = block_scan_excl(x, &total);
    if (b < nb) g_boff[b] = ex;
    if (b == 0) g_off[N_NODES] = E + N_NODES;
}

__global__ void scan3_kernel() {
    int i = blockIdx.x * blockDim.x + threadIdx.x;
    if (i >= N_NODES) return;
    int off = g_off[i] + g_boff[i >> 10];
    g_off[i] = off;
    g_cur[i] = off;
}

// ---------------- sort: scatter srcs into dst-grouped order ----------------
__global__ void scatter_kernel(const void* __restrict__ EI, int E) {
    int e = blockIdx.x * blockDim.x + threadIdx.x;
    int total = E + N_NODES;
    if (e >= total) return;
    int s, d;
    if (e < E) load_edge(EI, e, E, g_is64, s, d);
    else       s = d = e - E;
    int pos = atomicAdd(&g_cur[d], 1);
    g_ssrc[pos] = s;
}

// ---------------- K2: split-bf16 tensor-core GEMM + fused attention logits ----
#define GBM 128
#define GBN 64
#define GBK 64
#define SKP 72

__device__ __forceinline__ void ldsm_x4(uint32_t& r0, uint32_t& r1,
                                        uint32_t& r2, uint32_t& r3, uint32_t addr) {
    asm volatile("ldmatrix.sync.aligned.m8n8.x4.shared.b16 {%0,%1,%2,%3}, [%4];\n"
                 : "=r"(r0), "=r"(r1), "=r"(r2), "=r"(r3) : "r"(addr));
}

__device__ __forceinline__ void mma_bf16(float c[4], const uint32_t a[4],
                                         const uint32_t b[2]) {
    asm volatile(
        "mma.sync.aligned.m16n8k16.row.col.f32.bf16.bf16.f32 "
        "{%0,%1,%2,%3},{%4,%5,%6,%7},{%8,%9},{%0,%1,%2,%3};\n"
        : "+f"(c[0]), "+f"(c[1]), "+f"(c[2]), "+f"(c[3])
        : "r"(a[0]), "r"(a[1]), "r"(a[2]), "r"(a[3]), "r"(b[0]), "r"(b[1]));
}

__global__ __launch_bounds__(256, 2)
void gemm_bf16_kernel(const float* __restrict__ att_src,
                      const float* __restrict__ att_dst) {
    __shared__ __align__(16) __nv_bfloat16 sA[GBM][SKP];
    __shared__ __align__(16) __nv_bfloat16 sB[GBN][SKP];

    const int tid  = threadIdx.x;
    const int lane = tid & 31;
    const int warp = tid >> 5;
    const int wm = (warp & 3) * 32;
    const int wn = (warp >> 2) * 32;
    const int row0 = blockIdx.x * GBM;
    const int n0   = blockIdx.y * GBN;

    const uint32_t baseA = (uint32_t)__cvta_generic_to_shared(&sA[0][0]);
    const uint32_t baseB = (uint32_t)__cvta_generic_to_shared(&sB[0][0]);

    float acc[2][4][4];
    #pragma unroll
    for (int i = 0; i < 2; i++)
        #pragma unroll
        for (int j = 0; j < 4; j++)
            #pragma unroll
            for (int e = 0; e < 4; e++) acc[i][j][e] = 0.f;

    #pragma unroll 1
    for (int seg = 0; seg < 3; seg++) {
        const __nv_bfloat16* Aseg = (seg == 1) ? g_Al : g_Ah;
        const __nv_bfloat16* Bseg = (seg == 2) ? g_Btl : g_Bth;
        #pragma unroll 1
        for (int chunk = 0; chunk < 2; chunk++) {
            const int kk = chunk * GBK;
            __syncthreads();
            #pragma unroll
            for (int it = 0; it < 4; it++) {
                int slot = tid + it * 256;
                int r  = slot >> 3;
                int c8 = (slot & 7) * 8;
                uint4 v = make_uint4(0u, 0u, 0u, 0u);
                int gr = row0 + r;
                if (gr < N_NODES)
                    v = *(const uint4*)&Aseg[(size_t)gr * IN_DIM + kk + c8];
                *(uint4*)&sA[r][c8] = v;
            }
            #pragma unroll
            for (int it = 0; it < 2; it++) {
                int slot = tid + it * 256;
                int r  = slot >> 3;
                int c8 = (slot & 7) * 8;
                uint4 v = *(const uint4*)&Bseg[(size_t)(n0 + r) * IN_DIM + kk + c8];
                *(uint4*)&sB[r][c8] = v;
            }
            __syncthreads();

            #pragma unroll
            for (int k0 = 0; k0 < GBK; k0 += 16) {
                uint32_t a[2][4];
                #pragma unroll
                for (int i = 0; i < 2; i++) {
                    int r = wm + 16 * i + (lane & 15);
                    int c = k0 + ((lane & 16) ? 8 : 0);
                    ldsm_x4(a[i][0], a[i][1], a[i][2], a[i][3],
                            baseA + (uint32_t)(r * SKP + c) * 2u);
                }
                uint32_t b[4][2];
                #pragma unroll
                for (int jj = 0; jj < 2; jj++) {
                    int r = wn + jj * 16 + (lane & 7) + ((lane & 16) ? 8 : 0);
                    int c = k0 + ((lane & 8) ? 8 : 0);
                    uint32_t r0, r1, r2, r3;
                    ldsm_x4(r0, r1, r2, r3, baseB + (uint32_t)(r * SKP + c) * 2u);
                    b[2 * jj][0] = r0; b[2 * jj][1] = r1;
                    b[2 * jj + 1][0] = r2; b[2 * jj + 1][1] = r3;
                }
                #pragma unroll
                for (int i = 0; i < 2; i++)
                    #pragma unroll
                    for (int j = 0; j < 4; j++)
                        mma_bf16(acc[i][j], a[i], b[j]);
            }
        }
    }

    const int g   = lane >> 2;
    const int tig = lane & 3;
    const int head = blockIdx.y * 2 + (wn >> 5);

    float as_v[4][2], ad_v[4][2];
    #pragma unroll
    for (int j = 0; j < 4; j++) {
        int col = j * 8 + 2 * tig;
        as_v[j][0] = att_src[head * 32 + col];
        as_v[j][1] = att_src[head * 32 + col + 1];
        ad_v[j][0] = att_dst[head * 32 + col];
        ad_v[j][1] = att_dst[head * 32 + col + 1];
    }

    float ps[4] = {0.f, 0.f, 0.f, 0.f}, pd[4] = {0.f, 0.f, 0.f, 0.f};
    #pragma unroll
    for (int i = 0; i < 2; i++) {
        int row1 = row0 + wm + 16 * i + g;
        int row2 = row1 + 8;
        #pragma unroll
        for (int j = 0; j < 4; j++) {
            int colg = n0 + wn + j * 8 + 2 * tig;
            if (row1 < N_NODES)
                *(float2*)&g_h[(size_t)row1 * HF + colg] =
                    make_float2(acc[i][j][0], acc[i][j][1]);
            if (row2 < N_NODES)
                *(float2*)&g_h[(size_t)row2 * HF + colg] =
                    make_float2(acc[i][j][2], acc[i][j][3]);
            ps[2 * i]     += acc[i][j][0] * as_v[j][0] + acc[i][j][1] * as_v[j][1];
            ps[2 * i + 1] += acc[i][j][2] * as_v[j][0] + acc[i][j][3] * as_v[j][1];
            pd[2 * i]     += acc[i][j][0] * ad_v[j][0] + acc[i][j][1] * ad_v[j][1];
            pd[2 * i + 1] += acc[i][j][2] * ad_v[j][0] + acc[i][j][3] * ad_v[j][1];
        }
    }
    #pragma unroll
    for (int s = 0; s < 4; s++) {
        ps[s] += __shfl_xor_sync(0xffffffffu, ps[s], 1);
        ps[s] += __shfl_xor_sync(0xffffffffu, ps[s], 2);
        pd[s] += __shfl_xor_sync(0xffffffffu, pd[s], 1);
        pd[s] += __shfl_xor_sync(0xffffffffu, pd[s], 2);
    }
    if (tig == 0) {
        #pragma unroll
        for (int s = 0; s < 4; s++) {
            int row = row0 + wm + 16 * (s >> 1) + 8 * (s & 1) + g;
            if (row < N_NODES) {
                g_asrc[row * HEADS + head] = ps[s];
                g_adst[row * HEADS + head] = pd[s];
            }
        }
    }
}

// ---------------- K3: fused softmax + aggregation (warp per destination) ------
// Edges are dst-grouped; numerator and denominator accumulate in registers in
// one pass; single coalesced store per node. Max-shift skipped (logits O(10)).
__global__ void agg2_kernel(const float* __restrict__ bias,
                            float* __restrict__ out) {
    int wid  = (blockIdx.x * blockDim.x + threadIdx.x) >> 5;
    int lane = threadIdx.x & 31;
    if (wid >= N_NODES) return;
    const int d = wid;
    const int beg = g_off[d], end = g_off[d + 1];

    float adv = (lane < HEADS) ? g_adst[d * HEADS + lane] : 0.f;
    float num[8] = {0.f, 0.f, 0.f, 0.f, 0.f, 0.f, 0.f, 0.f};
    float den = 0.f;

    for (int i = beg; i < end; i++) {
        int s = __ldg(&g_ssrc[i]);
        float w = 0.f;
        if (lane < HEADS) {
            float x = __ldg(&g_asrc[s * HEADS + lane]) + adv;
            x = (x > 0.f) ? x : NEG_SLOPE * x;
            w = __expf(x);
            den += w;
        }
        const float* hr = &g_h[(size_t)s * HF];
        #pragma unroll
        for (int h = 0; h < HEADS; h++) {
            float wh = __shfl_sync(0xffffffffu, w, h);
            num[h] += wh * __ldg(&hr[h * 32 + lane]);
        }
    }

    float r = 0.f;
    #pragma unroll
    for (int h = 0; h < HEADS; h++) {
        float dh = __shfl_sync(0xffffffffu, den, h);
        r += num[h] / (dh + 1e-16f);
    }
    out[d * OUT_DIM + lane] = r * (1.0f / HEADS) + bias[lane];
}

// ---------------- launch ----------------
extern "C" void kernel_launch(void* const* d_in, const int* in_sizes, int n_in,
                              void* d_out, int out_size) {
    const float* X       = (const float*)d_in[0];
    const void*  EI      = d_in[1];
    const float* W       = (const float*)d_in[2];
    const float* att_src = (const float*)d_in[3];
    const float* att_dst = (const float*)d_in[4];
    const float* bias    = (const float*)d_in[5];
    float* out = (float*)d_out;

    int E = in_sizes[1] / 2;

    detect_kernel<<<1, 1>>>(EI);
    prep_kernel<<<(N_NODES * IN_DIM / 4 + 255) / 256, 256>>>(X);
    prepW_kernel<<<(IN_DIM * HF + 255) / 256, 256>>>(W);

    // counting sort by destination
    hist_kernel<<<(E + 255) / 256, 256>>>(EI, E);
    int nb = (N_NODES + 1023) / 1024;
    scan1_kernel<<<nb, 1024>>>();
    scan2_kernel<<<1, 1024>>>(nb, E);
    scan3_kernel<<<(N_NODES + 255) / 256, 256>>>();
    scatter_kernel<<<(E + N_NODES + 255) / 256, 256>>>(EI, E);

    dim3 ggrid((N_NODES + GBM - 1) / GBM, HF / GBN);
    gemm_bf16_kernel<<<ggrid, 256>>>(att_src, att_dst);

    agg2_kernel<<<(N_NODES * 32 + 255) / 256, 256>>>(bias, out);
}

// round 5
// speedup vs baseline: 2.0263x; 1.2795x over previous
#include <cuda_runtime.h>
#include <cuda_bf16.h>
#include <cuda_fp16.h>
#include <cstdint>

#define N_NODES 100000
#define IN_DIM  128
#define OUT_DIM 32
#define HEADS   8
#define HF      256   // HEADS*OUT_DIM
#define NEG_SLOPE 0.2f
#define MAX_SLOTS 1800000   // >= E + N_NODES

// ---------------- scratch (static device globals; no allocation) ----------------
__device__ __half g_hh[(size_t)N_NODES * HF];    // projected features, fp16 [N, H*F]
__device__ float g_asrc[N_NODES * HEADS];
__device__ float g_adst[N_NODES * HEADS];
__device__ int   g_is64;
__device__ __align__(256) __nv_bfloat16 g_Ah[(size_t)N_NODES * IN_DIM];
__device__ __align__(256) __nv_bfloat16 g_Al[(size_t)N_NODES * IN_DIM];
__device__ __align__(256) __nv_bfloat16 g_Bth[HF * IN_DIM];
__device__ __align__(256) __nv_bfloat16 g_Btl[HF * IN_DIM];
// counting sort by destination
__device__ int g_cnt[N_NODES];
__device__ int g_off[N_NODES + 1];
__device__ int g_cur[N_NODES];
__device__ int g_bsum[128];
__device__ int g_boff[128];
__device__ int g_ssrc[MAX_SLOTS];

// ---------------- K0: probe edge_index dtype ----------------
__global__ void detect_kernel(const void* EI) {
    const long long* p = (const long long*)EI;
    int is64 = 1;
    #pragma unroll
    for (int i = 0; i < 64; i++) {
        long long v = p[i];
        if (v < 0 || v >= N_NODES) is64 = 0;
    }
    g_is64 = is64;
}

__device__ __forceinline__ void load_edge(const void* EI, long long e, int E,
                                          int is64, int& s, int& d) {
    if (is64) {
        const long long* p = (const long long*)EI;
        s = (int)p[e]; d = (int)p[e + E];
    } else {
        const int* p = (const int*)EI;
        s = p[e]; d = p[e + E];
    }
}

// ---------------- K1a: split X into bf16 hi/lo + init degree counts ----------
__global__ void prep_kernel(const float* __restrict__ X) {
    int i = blockIdx.x * blockDim.x + threadIdx.x;
    if (i < N_NODES * IN_DIM / 4) {
        float4 v = ((const float4*)X)[i];
        __nv_bfloat16 h0 = __float2bfloat16(v.x);
        __nv_bfloat16 h1 = __float2bfloat16(v.y);
        __nv_bfloat16 h2 = __float2bfloat16(v.z);
        __nv_bfloat16 h3 = __float2bfloat16(v.w);
        __nv_bfloat16 l0 = __float2bfloat16(v.x - __bfloat162float(h0));
        __nv_bfloat16 l1 = __float2bfloat16(v.y - __bfloat162float(h1));
        __nv_bfloat16 l2 = __float2bfloat16(v.z - __bfloat162float(h2));
        __nv_bfloat16 l3 = __float2bfloat16(v.w - __bfloat162float(h3));
        ((__nv_bfloat162*)g_Ah)[2 * i]     = __nv_bfloat162(h0, h1);
        ((__nv_bfloat162*)g_Ah)[2 * i + 1] = __nv_bfloat162(h2, h3);
        ((__nv_bfloat162*)g_Al)[2 * i]     = __nv_bfloat162(l0, l1);
        ((__nv_bfloat162*)g_Al)[2 * i + 1] = __nv_bfloat162(l2, l3);
    }
    if (i < N_NODES) g_cnt[i] = 1;   // self loop
}

// ---------------- K1b: split + transpose W ----------------
__global__ void prepW_kernel(const float* __restrict__ W) {
    int i = blockIdx.x * blockDim.x + threadIdx.x;
    if (i >= IN_DIM * HF) return;
    int k = i >> 8;
    int n = i & 255;
    float x = W[i];
    __nv_bfloat16 hi = __float2bfloat16(x);
    __nv_bfloat16 lo = __float2bfloat16(x - __bfloat162float(hi));
    g_Bth[n * IN_DIM + k] = hi;
    g_Btl[n * IN_DIM + k] = lo;
}

// ---------------- sort: histogram ----------------
__global__ void hist_kernel(const void* __restrict__ EI, int E) {
    int e = blockIdx.x * blockDim.x + threadIdx.x;
    if (e >= E) return;
    int s, d;
    load_edge(EI, e, E, g_is64, s, d);
    atomicAdd(&g_cnt[d], 1);
}

// ---------------- sort: hierarchical exclusive scan ----------------
__device__ __forceinline__ int block_scan_excl(int x, int* total) {
    int lane = threadIdx.x & 31, w = threadIdx.x >> 5;
    int v = x;
    #pragma unroll
    for (int o = 1; o < 32; o <<= 1) {
        int t = __shfl_up_sync(0xffffffffu, v, o);
        if (lane >= o) v += t;
    }
    __shared__ int ws[32];
    if (lane == 31) ws[w] = v;
    __syncthreads();
    if (w == 0) {
        int u = ws[lane];
        #pragma unroll
        for (int o = 1; o < 32; o <<= 1) {
            int t = __shfl_up_sync(0xffffffffu, u, o);
            if (lane >= o) u += t;
        }
        ws[lane] = u;
    }
    __syncthreads();
    int incl = v + (w > 0 ? ws[w - 1] : 0);
    *total = ws[31];
    return incl - x;
}

__global__ void scan1_kernel() {
    int i = blockIdx.x * 1024 + threadIdx.x;
    int x = (i < N_NODES) ? g_cnt[i] : 0;
    int total;
    int ex = block_scan_excl(x, &total);
    if (i < N_NODES) g_off[i] = ex;
    if (threadIdx.x == 0) g_bsum[blockIdx.x] = total;
}

__global__ void scan2_kernel(int nb, int E) {
    int b = threadIdx.x;
    int x = (b < nb) ? g_bsum[b] : 0;
    int total;
    int ex = block_scan_excl(x, &total);
    if (b < nb) g_boff[b] = ex;
    if (b == 0) g_off[N_NODES] = E + N_NODES;
}

__global__ void scan3_kernel() {
    int i = blockIdx.x * blockDim.x + threadIdx.x;
    if (i >= N_NODES) return;
    int off = g_off[i] + g_boff[i >> 10];
    g_off[i] = off;
    g_cur[i] = off;
}

// ---------------- sort: scatter srcs into dst-grouped order ----------------
__global__ void scatter_kernel(const void* __restrict__ EI, int E) {
    int e = blockIdx.x * blockDim.x + threadIdx.x;
    int total = E + N_NODES;
    if (e >= total) return;
    int s, d;
    if (e < E) load_edge(EI, e, E, g_is64, s, d);
    else       s = d = e - E;
    int pos = atomicAdd(&g_cur[d], 1);
    g_ssrc[pos] = s;
}

// ---------------- K2: split-bf16 MMA GEMM, cp.async 2-stage, fused logits ----
// C(128x64 per block) = Xh*Wh + Xl*Wh + Xh*Wl over 6 (seg,chunk) iterations.
// smem: XOR-swizzled 128B rows (64 bf16), conflict-free for cp.async + ldmatrix.
#define GBM 128
#define GBN 64
#define GBK 64
#define A_STAGE_B (128 * 128)   // bytes per A stage
#define B_STAGE_B (64 * 128)    // bytes per B stage

__device__ __forceinline__ void ldsm_x4(uint32_t& r0, uint32_t& r1,
                                        uint32_t& r2, uint32_t& r3, uint32_t addr) {
    asm volatile("ldmatrix.sync.aligned.m8n8.x4.shared.b16 {%0,%1,%2,%3}, [%4];\n"
                 : "=r"(r0), "=r"(r1), "=r"(r2), "=r"(r3) : "r"(addr));
}

__device__ __forceinline__ void mma_bf16(float c[4], const uint32_t a[4],
                                         const uint32_t b[2]) {
    asm volatile(
        "mma.sync.aligned.m16n8k16.row.col.f32.bf16.bf16.f32 "
        "{%0,%1,%2,%3},{%4,%5,%6,%7},{%8,%9},{%0,%1,%2,%3};\n"
        : "+f"(c[0]), "+f"(c[1]), "+f"(c[2]), "+f"(c[3])
        : "r"(a[0]), "r"(a[1]), "r"(a[2]), "r"(a[3]), "r"(b[0]), "r"(b[1]));
}

__device__ __forceinline__ void cp16(uint32_t dst, const void* src, int srcsize) {
    asm volatile("cp.async.cg.shared.global [%0], [%1], 16, %2;\n"
                 :: "r"(dst), "l"(src), "r"(srcsize) : "memory");
}
__device__ __forceinline__ void cp_commit() {
    asm volatile("cp.async.commit_group;\n" ::: "memory");
}
template <int N>
__device__ __forceinline__ void cp_wait() {
    asm volatile("cp.async.wait_group %0;\n" :: "n"(N) : "memory");
}

__global__ __launch_bounds__(256, 2)
void gemm_bf16_kernel(const float* __restrict__ att_src,
                      const float* __restrict__ att_dst) {
    __shared__ __align__(16) __nv_bfloat16 sA[2][GBM][64];
    __shared__ __align__(16) __nv_bfloat16 sB[2][GBN][64];

    const int tid  = threadIdx.x;
    const int lane = tid & 31;
    const int warp = tid >> 5;
    const int wm = (warp & 3) * 32;
    const int wn = (warp >> 2) * 32;
    const int row0 = blockIdx.x * GBM;
    const int n0   = blockIdx.y * GBN;

    const uint32_t baseA = (uint32_t)__cvta_generic_to_shared(&sA[0][0][0]);
    const uint32_t baseB = (uint32_t)__cvta_generic_to_shared(&sB[0][0][0]);

    // issue cp.async for iteration `it` into stage it&1
    auto issue = [&](int it) {
        const int stage = it & 1;
        const int seg = it >> 1;
        const __nv_bfloat16* Aseg = (seg == 1) ? g_Al : g_Ah;
        const __nv_bfloat16* Bseg = (seg == 2) ? g_Btl : g_Bth;
        const int kk = (it & 1) * GBK;
        #pragma unroll
        for (int j = 0; j < 4; j++) {
            int slot = tid + j * 256;          // 0..1023
            int r  = slot >> 3;                // 0..127
            int cc = slot & 7;                 // 16B chunk in row
            int gr = row0 + r;
            const void* src = &Aseg[(size_t)min(gr, N_NODES - 1) * IN_DIM + kk + cc * 8];
            uint32_t dst = baseA + stage * A_STAGE_B + r * 128 + (cc ^ (r & 7)) * 16;
            cp16(dst, src, (gr < N_NODES) ? 16 : 0);
        }
        #pragma unroll
        for (int j = 0; j < 2; j++) {
            int slot = tid + j * 256;          // 0..511
            int r  = slot >> 3;                // 0..63
            int cc = slot & 7;
            const void* src = &Bseg[(size_t)(n0 + r) * IN_DIM + kk + cc * 8];
            uint32_t dst = baseB + stage * B_STAGE_B + r * 128 + (cc ^ (r & 7)) * 16;
            cp16(dst, src, 16);
        }
        cp_commit();
    };

    float acc[2][4][4];
    #pragma unroll
    for (int i = 0; i < 2; i++)
        #pragma unroll
        for (int j = 0; j < 4; j++)
            #pragma unroll
            for (int e = 0; e < 4; e++) acc[i][j][e] = 0.f;

    issue(0);

    #pragma unroll 1
    for (int it = 0; it < 6; it++) {
        const int stage = it & 1;
        if (it + 1 < 6) { issue(it + 1); cp_wait<1>(); }
        else            { cp_wait<0>(); }
        __syncthreads();

        const uint32_t aOff = baseA + stage * A_STAGE_B;
        const uint32_t bOff = baseB + stage * B_STAGE_B;
        #pragma unroll
        for (int k0 = 0; k0 < GBK; k0 += 16) {
            uint32_t a[2][4];
            #pragma unroll
            for (int i = 0; i < 2; i++) {
                int r = wm + 16 * i + (lane & 15);
                int cc = (k0 >> 3) + ((lane >> 4) & 1);
                ldsm_x4(a[i][0], a[i][1], a[i][2], a[i][3],
                        aOff + r * 128 + ((cc ^ (r & 7)) * 16));
            }
            uint32_t b[4][2];
            #pragma unroll
            for (int jj = 0; jj < 2; jj++) {
                int r = wn + jj * 16 + (lane & 7) + ((lane & 16) ? 8 : 0);
                int cc = (k0 >> 3) + ((lane >> 3) & 1);
                uint32_t r0, r1, r2, r3;
                ldsm_x4(r0, r1, r2, r3, bOff + r * 128 + ((cc ^ (r & 7)) * 16));
                b[2 * jj][0] = r0; b[2 * jj][1] = r1;
                b[2 * jj + 1][0] = r2; b[2 * jj + 1][1] = r3;
            }
            #pragma unroll
            for (int i = 0; i < 2; i++)
                #pragma unroll
                for (int j = 0; j < 4; j++)
                    mma_bf16(acc[i][j], a[i], b[j]);
        }
        __syncthreads();
    }

    // ---- epilogue: store h (fp16) + fused per-head attention logits ----
    const int g   = lane >> 2;
    const int tig = lane & 3;
    const int head = blockIdx.y * 2 + (wn >> 5);

    float as_v[4][2], ad_v[4][2];
    #pragma unroll
    for (int j = 0; j < 4; j++) {
        int col = j * 8 + 2 * tig;
        as_v[j][0] = att_src[head * 32 + col];
        as_v[j][1] = att_src[head * 32 + col + 1];
        ad_v[j][0] = att_dst[head * 32 + col];
        ad_v[j][1] = att_dst[head * 32 + col + 1];
    }

    float ps[4] = {0.f, 0.f, 0.f, 0.f}, pd[4] = {0.f, 0.f, 0.f, 0.f};
    #pragma unroll
    for (int i = 0; i < 2; i++) {
        int row1 = row0 + wm + 16 * i + g;
        int row2 = row1 + 8;
        #pragma unroll
        for (int j = 0; j < 4; j++) {
            int colg = n0 + wn + j * 8 + 2 * tig;
            if (row1 < N_NODES)
                *(__half2*)&g_hh[(size_t)row1 * HF + colg] =
                    __floats2half2_rn(acc[i][j][0], acc[i][j][1]);
            if (row2 < N_NODES)
                *(__half2*)&g_hh[(size_t)row2 * HF + colg] =
                    __floats2half2_rn(acc[i][j][2], acc[i][j][3]);
            ps[2 * i]     += acc[i][j][0] * as_v[j][0] + acc[i][j][1] * as_v[j][1];
            ps[2 * i + 1] += acc[i][j][2] * as_v[j][0] + acc[i][j][3] * as_v[j][1];
            pd[2 * i]     += acc[i][j][0] * ad_v[j][0] + acc[i][j][1] * ad_v[j][1];
            pd[2 * i + 1] += acc[i][j][2] * ad_v[j][0] + acc[i][j][3] * ad_v[j][1];
        }
    }
    #pragma unroll
    for (int s = 0; s < 4; s++) {
        ps[s] += __shfl_xor_sync(0xffffffffu, ps[s], 1);
        ps[s] += __shfl_xor_sync(0xffffffffu, ps[s], 2);
        pd[s] += __shfl_xor_sync(0xffffffffu, pd[s], 1);
        pd[s] += __shfl_xor_sync(0xffffffffu, pd[s], 2);
    }
    if (tig == 0) {
        #pragma unroll
        for (int s = 0; s < 4; s++) {
            int row = row0 + wm + 16 * (s >> 1) + 8 * (s & 1) + g;
            if (row < N_NODES) {
                g_asrc[row * HEADS + head] = ps[s];
                g_adst[row * HEADS + head] = pd[s];
            }
        }
    }
}

// ---------------- K3: fused softmax + aggregation (warp per destination) ------
__global__ void agg2_kernel(const float* __restrict__ bias,
                            float* __restrict__ out) {
    int wid  = (blockIdx.x * blockDim.x + threadIdx.x) >> 5;
    int lane = threadIdx.x & 31;
    if (wid >= N_NODES) return;
    const int d = wid;
    const int beg = g_off[d], end = g_off[d + 1];

    float adv = (lane < HEADS) ? g_adst[d * HEADS + lane] : 0.f;
    float num[8] = {0.f, 0.f, 0.f, 0.f, 0.f, 0.f, 0.f, 0.f};
    float den = 0.f;

    for (int i = beg; i < end; i++) {
        int s = __ldg(&g_ssrc[i]);
        float w = 0.f;
        if (lane < HEADS) {
            float x = __ldg(&g_asrc[s * HEADS + lane]) + adv;
            x = (x > 0.f) ? x : NEG_SLOPE * x;
            w = __expf(x);
            den += w;
        }
        const __half* hr = &g_hh[(size_t)s * HF];
        #pragma unroll
        for (int h = 0; h < HEADS; h++) {
            float wh = __shfl_sync(0xffffffffu, w, h);
            num[h] += wh * __half2float(__ldg(&hr[h * 32 + lane]));
        }
    }

    float r = 0.f;
    #pragma unroll
    for (int h = 0; h < HEADS; h++) {
        float dh = __shfl_sync(0xffffffffu, den, h);
        r += num[h] / (dh + 1e-16f);
    }
    out[d * OUT_DIM + lane] = r * (1.0f / HEADS) + bias[lane];
}

// ---------------- launch ----------------
extern "C" void kernel_launch(void* const* d_in, const int* in_sizes, int n_in,
                              void* d_out, int out_size) {
    const float* X       = (const float*)d_in[0];
    const void*  EI      = d_in[1];
    const float* W       = (const float*)d_in[2];
    const float* att_src = (const float*)d_in[3];
    const float* att_dst = (const float*)d_in[4];
    const float* bias    = (const float*)d_in[5];
    float* out = (float*)d_out;

    int E = in_sizes[1] / 2;

    detect_kernel<<<1, 1>>>(EI);
    prep_kernel<<<(N_NODES * IN_DIM / 4 + 255) / 256, 256>>>(X);
    prepW_kernel<<<(IN_DIM * HF + 255) / 256, 256>>>(W);

    // counting sort by destination
    hist_kernel<<<(E + 255) / 256, 256>>>(EI, E);
    int nb = (N_NODES + 1023) / 1024;
    scan1_kernel<<<nb, 1024>>>();
    scan2_kernel<<<1, 1024>>>(nb, E);
    scan3_kernel<<<(N_NODES + 255) / 256, 256>>>();
    scatter_kernel<<<(E + N_NODES + 255) / 256, 256>>>(EI, E);

    dim3 ggrid((N_NODES + GBM - 1) / GBM, HF / GBN);
    gemm_bf16_kernel<<<ggrid, 256>>>(att_src, att_dst);

    agg2_kernel<<<(N_NODES * 32 + 255) / 256, 256>>>(bias, out);
}

// round 6
// speedup vs baseline: 2.2536x; 1.1122x over previous
#include <cuda_runtime.h>
#include <cuda_bf16.h>
#include <cuda_fp16.h>
#include <cstdint>

#define N_NODES 100000
#define IN_DIM  128
#define OUT_DIM 32
#define HEADS   8
#define HF      256   // HEADS*OUT_DIM
#define NEG_SLOPE 0.2f
#define MAX_SLOTS 1800000   // >= E + N_NODES

// ---------------- scratch (static device globals; no allocation) ----------------
__device__ __align__(256) __half g_hh[(size_t)N_NODES * HF]; // fp16 h [N, H*F]
__device__ float g_asrc[N_NODES * HEADS];
__device__ float g_adst[N_NODES * HEADS];
__device__ int   g_is64;
__device__ __align__(256) __nv_bfloat16 g_Ah[(size_t)N_NODES * IN_DIM];
__device__ __align__(256) __nv_bfloat16 g_Al[(size_t)N_NODES * IN_DIM];
__device__ __align__(256) __nv_bfloat16 g_Bth[HF * IN_DIM];
__device__ __align__(256) __nv_bfloat16 g_Btl[HF * IN_DIM];
// counting sort by destination
__device__ int g_cnt[N_NODES];
__device__ int g_off[N_NODES + 1];
__device__ int g_cur[N_NODES];
__device__ int g_bsum[128];
__device__ int g_boff[128];
__device__ int g_ssrc[MAX_SLOTS];

// ---------------- K0: probe edge_index dtype ----------------
__global__ void detect_kernel(const void* EI) {
    const long long* p = (const long long*)EI;
    int is64 = 1;
    #pragma unroll
    for (int i = 0; i < 64; i++) {
        long long v = p[i];
        if (v < 0 || v >= N_NODES) is64 = 0;
    }
    g_is64 = is64;
}

__device__ __forceinline__ void load_edge(const void* EI, long long e, int E,
                                          int is64, int& s, int& d) {
    if (is64) {
        const long long* p = (const long long*)EI;
        s = (int)p[e]; d = (int)p[e + E];
    } else {
        const int* p = (const int*)EI;
        s = p[e]; d = p[e + E];
    }
}

// ---------------- K1a: split X into bf16 hi/lo + init degree counts ----------
__global__ void prep_kernel(const float* __restrict__ X) {
    int i = blockIdx.x * blockDim.x + threadIdx.x;
    if (i < N_NODES * IN_DIM / 4) {
        float4 v = ((const float4*)X)[i];
        __nv_bfloat16 h0 = __float2bfloat16(v.x);
        __nv_bfloat16 h1 = __float2bfloat16(v.y);
        __nv_bfloat16 h2 = __float2bfloat16(v.z);
        __nv_bfloat16 h3 = __float2bfloat16(v.w);
        __nv_bfloat16 l0 = __float2bfloat16(v.x - __bfloat162float(h0));
        __nv_bfloat16 l1 = __float2bfloat16(v.y - __bfloat162float(h1));
        __nv_bfloat16 l2 = __float2bfloat16(v.z - __bfloat162float(h2));
        __nv_bfloat16 l3 = __float2bfloat16(v.w - __bfloat162float(h3));
        ((__nv_bfloat162*)g_Ah)[2 * i]     = __nv_bfloat162(h0, h1);
        ((__nv_bfloat162*)g_Ah)[2 * i + 1] = __nv_bfloat162(h2, h3);
        ((__nv_bfloat162*)g_Al)[2 * i]     = __nv_bfloat162(l0, l1);
        ((__nv_bfloat162*)g_Al)[2 * i + 1] = __nv_bfloat162(l2, l3);
    }
    if (i < N_NODES) g_cnt[i] = 1;   // self loop
}

// ---------------- K1b: split + transpose W ----------------
__global__ void prepW_kernel(const float* __restrict__ W) {
    int i = blockIdx.x * blockDim.x + threadIdx.x;
    if (i >= IN_DIM * HF) return;
    int k = i >> 8;
    int n = i & 255;
    float x = W[i];
    __nv_bfloat16 hi = __float2bfloat16(x);
    __nv_bfloat16 lo = __float2bfloat16(x - __bfloat162float(hi));
    g_Bth[n * IN_DIM + k] = hi;
    g_Btl[n * IN_DIM + k] = lo;
}

// ---------------- sort: histogram (4 edges per thread, coalesced, MLP=4) -----
__global__ void hist_kernel(const void* __restrict__ EI, int E) {
    int base = blockIdx.x * (blockDim.x * 4) + threadIdx.x;
    int is64 = g_is64;
    #pragma unroll
    for (int k = 0; k < 4; k++) {
        int e = base + k * blockDim.x;
        if (e < E) {
            int d;
            if (is64) d = (int)((const long long*)EI)[e + E];
            else      d = ((const int*)EI)[e + E];
            atomicAdd(&g_cnt[d], 1);
        }
    }
}

// ---------------- sort: hierarchical exclusive scan ----------------
__device__ __forceinline__ int block_scan_excl(int x, int* total) {
    int lane = threadIdx.x & 31, w = threadIdx.x >> 5;
    int v = x;
    #pragma unroll
    for (int o = 1; o < 32; o <<= 1) {
        int t = __shfl_up_sync(0xffffffffu, v, o);
        if (lane >= o) v += t;
    }
    __shared__ int ws[32];
    if (lane == 31) ws[w] = v;
    __syncthreads();
    if (w == 0) {
        int u = ws[lane];
        #pragma unroll
        for (int o = 1; o < 32; o <<= 1) {
            int t = __shfl_up_sync(0xffffffffu, u, o);
            if (lane >= o) u += t;
        }
        ws[lane] = u;
    }
    __syncthreads();
    int incl = v + (w > 0 ? ws[w - 1] : 0);
    *total = ws[31];
    return incl - x;
}

__global__ void scan1_kernel() {
    int i = blockIdx.x * 1024 + threadIdx.x;
    int x = (i < N_NODES) ? g_cnt[i] : 0;
    int total;
    int ex = block_scan_excl(x, &total);
    if (i < N_NODES) g_off[i] = ex;
    if (threadIdx.x == 0) g_bsum[blockIdx.x] = total;
}

__global__ void scan2_kernel(int nb, int E) {
    int b = threadIdx.x;
    int x = (b < nb) ? g_bsum[b] : 0;
    int total;
    int ex = block_scan_excl(x, &total);
    if (b < nb) g_boff[b] = ex;
    if (b == 0) g_off[N_NODES] = E + N_NODES;
}

__global__ void scan3_kernel() {
    int i = blockIdx.x * blockDim.x + threadIdx.x;
    if (i >= N_NODES) return;
    int off = g_off[i] + g_boff[i >> 10];
    g_off[i] = off;
    g_cur[i] = off;
}

// ---------------- sort: scatter (4 edges per thread) ----------------
__global__ void scatter_kernel(const void* __restrict__ EI, int E) {
    int base = blockIdx.x * (blockDim.x * 4) + threadIdx.x;
    int is64 = g_is64;
    int total = E + N_NODES;
    #pragma unroll
    for (int k = 0; k < 4; k++) {
        int e = base + k * blockDim.x;
        if (e < total) {
            int s, d;
            if (e < E) load_edge(EI, e, E, is64, s, d);
            else       s = d = e - E;
            int pos = atomicAdd(&g_cur[d], 1);
            g_ssrc[pos] = s;
        }
    }
}

// ---------------- K2: split-bf16 MMA GEMM, cp.async 2-stage, fused logits ----
#define GBM 128
#define GBN 64
#define GBK 64
#define A_STAGE_B (128 * 128)
#define B_STAGE_B (64 * 128)

__device__ __forceinline__ void ldsm_x4(uint32_t& r0, uint32_t& r1,
                                        uint32_t& r2, uint32_t& r3, uint32_t addr) {
    asm volatile("ldmatrix.sync.aligned.m8n8.x4.shared.b16 {%0,%1,%2,%3}, [%4];\n"
                 : "=r"(r0), "=r"(r1), "=r"(r2), "=r"(r3) : "r"(addr));
}

__device__ __forceinline__ void mma_bf16(float c[4], const uint32_t a[4],
                                         const uint32_t b[2]) {
    asm volatile(
        "mma.sync.aligned.m16n8k16.row.col.f32.bf16.bf16.f32 "
        "{%0,%1,%2,%3},{%4,%5,%6,%7},{%8,%9},{%0,%1,%2,%3};\n"
        : "+f"(c[0]), "+f"(c[1]), "+f"(c[2]), "+f"(c[3])
        : "r"(a[0]), "r"(a[1]), "r"(a[2]), "r"(a[3]), "r"(b[0]), "r"(b[1]));
}

__device__ __forceinline__ void cp16(uint32_t dst, const void* src, int srcsize) {
    asm volatile("cp.async.cg.shared.global [%0], [%1], 16, %2;\n"
                 :: "r"(dst), "l"(src), "r"(srcsize) : "memory");
}
__device__ __forceinline__ void cp_commit() {
    asm volatile("cp.async.commit_group;\n" ::: "memory");
}
template <int N>
__device__ __forceinline__ void cp_wait() {
    asm volatile("cp.async.wait_group %0;\n" :: "n"(N) : "memory");
}

__global__ __launch_bounds__(256, 2)
void gemm_bf16_kernel(const float* __restrict__ att_src,
                      const float* __restrict__ att_dst) {
    __shared__ __align__(16) __nv_bfloat16 sA[2][GBM][64];
    __shared__ __align__(16) __nv_bfloat16 sB[2][GBN][64];

    const int tid  = threadIdx.x;
    const int lane = tid & 31;
    const int warp = tid >> 5;
    const int wm = (warp & 3) * 32;
    const int wn = (warp >> 2) * 32;
    const int row0 = blockIdx.x * GBM;
    const int n0   = blockIdx.y * GBN;

    const uint32_t baseA = (uint32_t)__cvta_generic_to_shared(&sA[0][0][0]);
    const uint32_t baseB = (uint32_t)__cvta_generic_to_shared(&sB[0][0][0]);

    auto issue = [&](int it) {
        const int stage = it & 1;
        const int seg = it >> 1;
        const __nv_bfloat16* Aseg = (seg == 1) ? g_Al : g_Ah;
        const __nv_bfloat16* Bseg = (seg == 2) ? g_Btl : g_Bth;
        const int kk = (it & 1) * GBK;
        #pragma unroll
        for (int j = 0; j < 4; j++) {
            int slot = tid + j * 256;
            int r  = slot >> 3;
            int cc = slot & 7;
            int gr = row0 + r;
            const void* src = &Aseg[(size_t)min(gr, N_NODES - 1) * IN_DIM + kk + cc * 8];
            uint32_t dst = baseA + stage * A_STAGE_B + r * 128 + (cc ^ (r & 7)) * 16;
            cp16(dst, src, (gr < N_NODES) ? 16 : 0);
        }
        #pragma unroll
        for (int j = 0; j < 2; j++) {
            int slot = tid + j * 256;
            int r  = slot >> 3;
            int cc = slot & 7;
            const void* src = &Bseg[(size_t)(n0 + r) * IN_DIM + kk + cc * 8];
            uint32_t dst = baseB + stage * B_STAGE_B + r * 128 + (cc ^ (r & 7)) * 16;
            cp16(dst, src, 16);
        }
        cp_commit();
    };

    float acc[2][4][4];
    #pragma unroll
    for (int i = 0; i < 2; i++)
        #pragma unroll
        for (int j = 0; j < 4; j++)
            #pragma unroll
            for (int e = 0; e < 4; e++) acc[i][j][e] = 0.f;

    issue(0);

    #pragma unroll 1
    for (int it = 0; it < 6; it++) {
        const int stage = it & 1;
        if (it + 1 < 6) { issue(it + 1); cp_wait<1>(); }
        else            { cp_wait<0>(); }
        __syncthreads();

        const uint32_t aOff = baseA + stage * A_STAGE_B;
        const uint32_t bOff = baseB + stage * B_STAGE_B;
        #pragma unroll
        for (int k0 = 0; k0 < GBK; k0 += 16) {
            uint32_t a[2][4];
            #pragma unroll
            for (int i = 0; i < 2; i++) {
                int r = wm + 16 * i + (lane & 15);
                int cc = (k0 >> 3) + ((lane >> 4) & 1);
                ldsm_x4(a[i][0], a[i][1], a[i][2], a[i][3],
                        aOff + r * 128 + ((cc ^ (r & 7)) * 16));
            }
            uint32_t b[4][2];
            #pragma unroll
            for (int jj = 0; jj < 2; jj++) {
                int r = wn + jj * 16 + (lane & 7) + ((lane & 16) ? 8 : 0);
                int cc = (k0 >> 3) + ((lane >> 3) & 1);
                uint32_t r0, r1, r2, r3;
                ldsm_x4(r0, r1, r2, r3, bOff + r * 128 + ((cc ^ (r & 7)) * 16));
                b[2 * jj][0] = r0; b[2 * jj][1] = r1;
                b[2 * jj + 1][0] = r2; b[2 * jj + 1][1] = r3;
            }
            #pragma unroll
            for (int i = 0; i < 2; i++)
                #pragma unroll
                for (int j = 0; j < 4; j++)
                    mma_bf16(acc[i][j], a[i], b[j]);
        }
        __syncthreads();
    }

    // ---- epilogue: store h (fp16) + fused per-head attention logits ----
    const int g   = lane >> 2;
    const int tig = lane & 3;
    const int head = blockIdx.y * 2 + (wn >> 5);

    float as_v[4][2], ad_v[4][2];
    #pragma unroll
    for (int j = 0; j < 4; j++) {
        int col = j * 8 + 2 * tig;
        as_v[j][0] = att_src[head * 32 + col];
        as_v[j][1] = att_src[head * 32 + col + 1];
        ad_v[j][0] = att_dst[head * 32 + col];
        ad_v[j][1] = att_dst[head * 32 + col + 1];
    }

    float ps[4] = {0.f, 0.f, 0.f, 0.f}, pd[4] = {0.f, 0.f, 0.f, 0.f};
    #pragma unroll
    for (int i = 0; i < 2; i++) {
        int row1 = row0 + wm + 16 * i + g;
        int row2 = row1 + 8;
        #pragma unroll
        for (int j = 0; j < 4; j++) {
            int colg = n0 + wn + j * 8 + 2 * tig;
            if (row1 < N_NODES)
                *(__half2*)&g_hh[(size_t)row1 * HF + colg] =
                    __floats2half2_rn(acc[i][j][0], acc[i][j][1]);
            if (row2 < N_NODES)
                *(__half2*)&g_hh[(size_t)row2 * HF + colg] =
                    __floats2half2_rn(acc[i][j][2], acc[i][j][3]);
            ps[2 * i]     += acc[i][j][0] * as_v[j][0] + acc[i][j][1] * as_v[j][1];
            ps[2 * i + 1] += acc[i][j][2] * as_v[j][0] + acc[i][j][3] * as_v[j][1];
            pd[2 * i]     += acc[i][j][0] * ad_v[j][0] + acc[i][j][1] * ad_v[j][1];
            pd[2 * i + 1] += acc[i][j][2] * ad_v[j][0] + acc[i][j][3] * ad_v[j][1];
        }
    }
    #pragma unroll
    for (int s = 0; s < 4; s++) {
        ps[s] += __shfl_xor_sync(0xffffffffu, ps[s], 1);
        ps[s] += __shfl_xor_sync(0xffffffffu, ps[s], 2);
        pd[s] += __shfl_xor_sync(0xffffffffu, pd[s], 1);
        pd[s] += __shfl_xor_sync(0xffffffffu, pd[s], 2);
    }
    if (tig == 0) {
        #pragma unroll
        for (int s = 0; s < 4; s++) {
            int row = row0 + wm + 16 * (s >> 1) + 8 * (s & 1) + g;
            if (row < N_NODES) {
                g_asrc[row * HEADS + head] = ps[s];
                g_adst[row * HEADS + head] = pd[s];
            }
        }
    }
}

// ---------------- K3: fused softmax + aggregation (warp per destination) ------
// Lane l owns halves [8l, 8l+8) of each 512B h-row: head l>>2, feats (l&3)*8+.
// One LDG.128 + one SHFL per edge per lane; xor-reduce across heads at the end.
__global__ void agg2_kernel(const float* __restrict__ bias,
                            float* __restrict__ out) {
    int wid  = (blockIdx.x * blockDim.x + threadIdx.x) >> 5;
    int lane = threadIdx.x & 31;
    if (wid >= N_NODES) return;
    const int d = wid;
    const int beg = g_off[d], end = g_off[d + 1];
    const int hd = lane >> 2;

    float adv = (lane < HEADS) ? g_adst[d * HEADS + lane] : 0.f;
    float num[8] = {0.f, 0.f, 0.f, 0.f, 0.f, 0.f, 0.f, 0.f};
    float den = 0.f;

    auto body = [&](int s, float w) {
        float wh = __shfl_sync(0xffffffffu, w, hd);
        uint4 v = __ldg((const uint4*)&g_hh[(size_t)s * HF + lane * 8]);
        const __half2* hp = (const __half2*)&v;
        #pragma unroll
        for (int k = 0; k < 4; k++) {
            float2 f = __half22float2(hp[k]);
            num[2 * k]     += wh * f.x;
            num[2 * k + 1] += wh * f.y;
        }
    };
    auto weight = [&](int s) -> float {
        float w = 0.f;
        if (lane < HEADS) {
            float x = __ldg(&g_asrc[s * HEADS + lane]) + adv;
            x = (x > 0.f) ? x : NEG_SLOPE * x;
            w = __expf(x);
            den += w;
        }
        return w;
    };

    int i = beg;
    for (; i + 2 <= end; i += 2) {
        int s0 = __ldg(&g_ssrc[i]);
        int s1 = __ldg(&g_ssrc[i + 1]);
        float w0 = weight(s0);
        float w1 = weight(s1);
        body(s0, w0);
        body(s1, w1);
    }
    if (i < end) {
        int s0 = __ldg(&g_ssrc[i]);
        body(s0, weight(s0));
    }

    // divide by this head's denominator, then sum across heads (lanes stride 4)
    float dh = __shfl_sync(0xffffffffu, den, hd);
    float inv = 1.0f / (dh + 1e-16f);
    #pragma unroll
    for (int j = 0; j < 8; j++) {
        float c = num[j] * inv;
        c += __shfl_xor_sync(0xffffffffu, c, 4);
        c += __shfl_xor_sync(0xffffffffu, c, 8);
        c += __shfl_xor_sync(0xffffffffu, c, 16);
        num[j] = c;
    }
    if (lane < 4) {
        float4 b0 = ((const float4*)bias)[lane * 2];
        float4 b1 = ((const float4*)bias)[lane * 2 + 1];
        float4 o0 = make_float4(num[0] * 0.125f + b0.x, num[1] * 0.125f + b0.y,
                                num[2] * 0.125f + b0.z, num[3] * 0.125f + b0.w);
        float4 o1 = make_float4(num[4] * 0.125f + b1.x, num[5] * 0.125f + b1.y,
                                num[6] * 0.125f + b1.z, num[7] * 0.125f + b1.w);
        ((float4*)&out[d * OUT_DIM])[lane * 2]     = o0;
        ((float4*)&out[d * OUT_DIM])[lane * 2 + 1] = o1;
    }
}

// ---------------- launch ----------------
extern "C" void kernel_launch(void* const* d_in, const int* in_sizes, int n_in,
                              void* d_out, int out_size) {
    const float* X       = (const float*)d_in[0];
    const void*  EI      = d_in[1];
    const float* W       = (const float*)d_in[2];
    const float* att_src = (const float*)d_in[3];
    const float* att_dst = (const float*)d_in[4];
    const float* bias    = (const float*)d_in[5];
    float* out = (float*)d_out;

    int E = in_sizes[1] / 2;

    detect_kernel<<<1, 1>>>(EI);
    prep_kernel<<<(N_NODES * IN_DIM / 4 + 255) / 256, 256>>>(X);
    prepW_kernel<<<(IN_DIM * HF + 255) / 256, 256>>>(W);

    // counting sort by destination
    hist_kernel<<<(E + 1023) / 1024, 256>>>(EI, E);
    int nb = (N_NODES + 1023) / 1024;
    scan1_kernel<<<nb, 1024>>>();
    scan2_kernel<<<1, 1024>>>(nb, E);
    scan3_kernel<<<(N_NODES + 255) / 256, 256>>>();
    scatter_kernel<<<(E + N_NODES + 1023) / 1024, 256>>>(EI, E);

    dim3 ggrid((N_NODES + GBM - 1) / GBM, HF / GBN);
    gemm_bf16_kernel<<<ggrid, 256>>>(att_src, att_dst);

    agg2_kernel<<<(N_NODES * 32 + 255) / 256, 256>>>(bias, out);
}